// round 3
// baseline (speedup 1.0000x reference)
#include <cuda_runtime.h>
#include <math.h>

#define BB   128
#define HH   4
#define NN   8192
#define DD   64
#define NT   16          // tiles per batch
#define TILE 512         // rows per tile (NT*TILE == NN)
#define EPSF 1e-8f
#define NEGINF (-3.0e38f)

// Scratch: per-(b, tile, head8) top-8 candidates (value, global index)
__device__ float g_cand_v[BB * NT * 8 * 8];
__device__ int   g_cand_i[BB * NT * 8 * 8];

// ---------------------------------------------------------------------------
// Sorted-descending top-8 insertion (all static register indices)
// ---------------------------------------------------------------------------
__device__ __forceinline__ void insert8(float v, int idx, float tv[8], int ti[8]) {
    if (v <= tv[7]) return;
    tv[7] = v; ti[7] = idx;
#pragma unroll
    for (int s = 7; s > 0; --s) {
        if (tv[s] > tv[s-1]) {
            float t = tv[s]; tv[s] = tv[s-1]; tv[s-1] = t;
            int t2 = ti[s]; ti[s] = ti[s-1]; ti[s-1] = t2;
        }
    }
}

__device__ __forceinline__ void cswap(float& a, int& ai, float& b, int& bi) {
    if (b > a) { float t = a; a = b; b = t; int t2 = ai; ai = bi; bi = t2; }
}

// Butterfly merge of per-lane sorted top-8 lists across the warp.
// After 5 stages every lane holds the warp-global top-8, sorted descending.
__device__ __forceinline__ void warp_merge8(float tv[8], int ti[8]) {
#pragma unroll
    for (int off = 16; off >= 1; off >>= 1) {
        float ov[8]; int oi[8];
#pragma unroll
        for (int k = 0; k < 8; ++k) {
            ov[k] = __shfl_xor_sync(0xffffffffu, tv[k], off);
            oi[k] = __shfl_xor_sync(0xffffffffu, ti[k], off);
        }
        // top-8 of the two sorted lists: max(A[k], B[7-k]) yields a bitonic seq
        float nv[8]; int ni[8];
#pragma unroll
        for (int k = 0; k < 8; ++k) {
            if (tv[k] >= ov[7-k]) { nv[k] = tv[k];   ni[k] = ti[k];   }
            else                  { nv[k] = ov[7-k]; ni[k] = oi[7-k]; }
        }
        // bitonic sort (desc) of the 8 bitonic elements: stages 4, 2, 1
        cswap(nv[0],ni[0],nv[4],ni[4]); cswap(nv[1],ni[1],nv[5],ni[5]);
        cswap(nv[2],ni[2],nv[6],ni[6]); cswap(nv[3],ni[3],nv[7],ni[7]);
        cswap(nv[0],ni[0],nv[2],ni[2]); cswap(nv[1],ni[1],nv[3],ni[3]);
        cswap(nv[4],ni[4],nv[6],ni[6]); cswap(nv[5],ni[5],nv[7],ni[7]);
        cswap(nv[0],ni[0],nv[1],ni[1]); cswap(nv[2],ni[2],nv[3],ni[3]);
        cswap(nv[4],ni[4],nv[5],ni[5]); cswap(nv[6],ni[6],nv[7],ni[7]);
#pragma unroll
        for (int k = 0; k < 8; ++k) { tv[k] = nv[k]; ti[k] = ni[k]; }
    }
}

// ---------------------------------------------------------------------------
// K1: single streaming pass over memory.
//  - writes new_memory = 4*memory
//  - computes cosine sims vs 8 keys (4 read + 4 write) per row
//  - per-tile top-8 candidates per head -> global scratch
//  - zeroes this tile's slices of the dense r_w / w_w outputs
// ---------------------------------------------------------------------------
__global__ __launch_bounds__(256)
void k1_stream(const float* __restrict__ mem,
               const float* __restrict__ rk,
               const float* __restrict__ wk,
               float* __restrict__ new_mem,
               float* __restrict__ o_rw,
               float* __restrict__ o_ww)
{
    __shared__ float s_sim[TILE * 8];   // 16 KB: sim[row_in_tile][head8]
    __shared__ float s_knorm[8];

    const int b    = blockIdx.y;
    const int tile = blockIdx.x;
    const int tid  = threadIdx.x;
    const int lane = tid & 31;
    const int warp = tid >> 5;          // 8 warps
    const int j    = lane & 7;          // dim-slice within row
    const int rsub = lane >> 3;         // row within 4-row group

    // Zero the dense weight slices owned by this (b, tile)
    {
        const size_t nb = (size_t)tile * TILE;
        for (int i = tid; i < HH * TILE; i += 256) {
            const int h  = i >> 9;              // TILE == 512
            const int nn = i & (TILE - 1);
            const size_t o = ((size_t)b * HH + h) * NN + nb + nn;
            o_rw[o] = 0.f;
            o_ww[o] = 0.f;
        }
    }

    // Key norms (8 keys, one thread each)
    if (tid < 8) {
        const float* kp = (tid < 4) ? rk + ((size_t)b * HH + tid) * DD
                                    : wk + ((size_t)b * HH + (tid - 4)) * DD;
        float s = 0.f;
        for (int d = 0; d < DD; ++d) s += kp[d] * kp[d];
        s_knorm[tid] = fmaxf(sqrtf(s), EPSF);
    }

    // This lane's 8-dim slice of every key -> registers
    float kreg[8][8];
#pragma unroll
    for (int h8 = 0; h8 < 8; ++h8) {
        const float* kp = (h8 < 4) ? rk + ((size_t)b * HH + h8) * DD
                                   : wk + ((size_t)b * HH + (h8 - 4)) * DD;
        const float4* kp4 = (const float4*)(kp + 8 * j);
        float4 ka = kp4[0], kb = kp4[1];
        kreg[h8][0]=ka.x; kreg[h8][1]=ka.y; kreg[h8][2]=ka.z; kreg[h8][3]=ka.w;
        kreg[h8][4]=kb.x; kreg[h8][5]=kb.y; kreg[h8][6]=kb.z; kreg[h8][7]=kb.w;
    }
    __syncthreads();
    const float knj = s_knorm[j];   // lane j is responsible for head j's sim

    const float* mb = mem     + ((size_t)b * NN + (size_t)tile * TILE) * DD;
    float*       ob = new_mem + ((size_t)b * NN + (size_t)tile * TILE) * DD;

    for (int it = warp * 4; it < TILE; it += 32) {
        const int r = it + rsub;
        const float4* p = (const float4*)(mb + (size_t)r * DD + j * 8);
        float4 x0 = p[0], x1 = p[1];

        float4* q = (float4*)(ob + (size_t)r * DD + j * 8);
        q[0] = make_float4(4.f*x0.x, 4.f*x0.y, 4.f*x0.z, 4.f*x0.w);
        q[1] = make_float4(4.f*x1.x, 4.f*x1.y, 4.f*x1.z, 4.f*x1.w);

        float nrm = x0.x*x0.x + x0.y*x0.y + x0.z*x0.z + x0.w*x0.w
                  + x1.x*x1.x + x1.y*x1.y + x1.z*x1.z + x1.w*x1.w;
        float dot[8];
#pragma unroll
        for (int h = 0; h < 8; ++h) {
            dot[h] = kreg[h][0]*x0.x + kreg[h][1]*x0.y + kreg[h][2]*x0.z + kreg[h][3]*x0.w
                   + kreg[h][4]*x1.x + kreg[h][5]*x1.y + kreg[h][6]*x1.z + kreg[h][7]*x1.w;
        }
        // all-reduce over the 8 lanes sharing this row
#pragma unroll
        for (int off = 4; off >= 1; off >>= 1) {
            nrm += __shfl_xor_sync(0xffffffffu, nrm, off);
#pragma unroll
            for (int h = 0; h < 8; ++h)
                dot[h] += __shfl_xor_sync(0xffffffffu, dot[h], off);
        }
        // lane j takes head j's dot (static select tree, no dynamic reg index)
        float a0 = (j&1)?dot[1]:dot[0], a1 = (j&1)?dot[3]:dot[2];
        float a2 = (j&1)?dot[5]:dot[4], a3 = (j&1)?dot[7]:dot[6];
        float b0 = (j&2)?a1:a0,         b1 = (j&2)?a3:a2;
        float dj = (j&4)?b1:b0;

        const float mn  = fmaxf(sqrtf(nrm), EPSF);
        const float sim = 10.f * __fdividef(dj, knj * mn + EPSF);
        s_sim[r * 8 + j] = sim;
    }
    __syncthreads();

    // Per-head top-8 within this tile: warp w handles head w
    float tv[8]; int ti[8];
#pragma unroll
    for (int k = 0; k < 8; ++k) { tv[k] = NEGINF; ti[k] = 0; }
    for (int r = lane; r < TILE; r += 32)
        insert8(s_sim[r * 8 + warp], tile * TILE + r, tv, ti);
    warp_merge8(tv, ti);

    if (lane == 0) {
        const int o = (((b * NT + tile) * 8) + warp) * 8;
#pragma unroll
        for (int k = 0; k < 8; ++k) { g_cand_v[o + k] = tv[k]; g_cand_i[o + k] = ti[k]; }
    }
}

// ---------------------------------------------------------------------------
// K2: per (b, head8) warp — merge tile candidates into exact top-8, softmax,
// scatter dense weights, apply read gather / write fix-ups.
// ---------------------------------------------------------------------------
__global__ __launch_bounds__(256)
void k2_apply(const float* __restrict__ mem,
              const float* __restrict__ wv,
              const float* __restrict__ er,
              float* __restrict__ o_rc,
              float* __restrict__ o_rw,
              float* __restrict__ new_mem,
              float* __restrict__ o_ww)
{
    __shared__ float s_rc[4][DD];

    const int b    = blockIdx.x;
    const int tid  = threadIdx.x;
    const int lane = tid & 31;
    const int h8   = tid >> 5;          // 8 warps -> 8 (b, head8) rows

    float tv[8]; int ti[8];
#pragma unroll
    for (int k = 0; k < 8; ++k) { tv[k] = NEGINF; ti[k] = 0; }

    for (int e = lane; e < NT * 8; e += 32) {
        const int tile = e >> 3, k = e & 7;
        const int o = (((b * NT + tile) * 8) + h8) * 8 + k;
        insert8(g_cand_v[o], g_cand_i[o], tv, ti);
    }
    warp_merge8(tv, ti);   // every lane now holds the row's exact top-8

    // softmax over the 8 survivors (the rest underflow to exactly 0 in ref)
    float w[8]; float s = 0.f;
#pragma unroll
    for (int k = 0; k < 8; ++k) { w[k] = expf(tv[k] - tv[0]); s += w[k]; }
    const float inv = __fdividef(1.f, s);
#pragma unroll
    for (int k = 0; k < 8; ++k) w[k] *= inv;

    // scatter dense weights
    if (lane == 0) {
        float* dense = (h8 < 4) ? o_rw + ((size_t)b * HH + h8) * NN
                                : o_ww + ((size_t)b * HH + (h8 - 4)) * NN;
#pragma unroll
        for (int k = 0; k < 8; ++k) dense[ti[k]] = w[k];
    }

    const int d = lane * 2;
    if (h8 < 4) {
        // read head: read_combined contribution
        float ax = 0.f, ay = 0.f;
#pragma unroll
        for (int k = 0; k < 8; ++k) {
            const float2 m2 = *(const float2*)(mem + ((size_t)b * NN + ti[k]) * DD + d);
            ax += w[k] * m2.x;
            ay += w[k] * m2.y;
        }
        s_rc[h8][d]     = 0.25f * ax;
        s_rc[h8][d + 1] = 0.25f * ay;
    } else {
        // write head: fix up the 8 selected new_memory rows
        const int h = h8 - 4;
        const float2 e2 = *(const float2*)(er + ((size_t)b * HH + h) * DD + d);
        const float2 v2 = *(const float2*)(wv + ((size_t)b * HH + h) * DD + d);
#pragma unroll
        for (int k = 0; k < 8; ++k) {
            const float2 m2 = *(const float2*)(mem + ((size_t)b * NN + ti[k]) * DD + d);
            float* dst = new_mem + ((size_t)b * NN + ti[k]) * DD + d;
            atomicAdd(dst,     w[k] * (v2.x - m2.x * e2.x));
            atomicAdd(dst + 1, w[k] * (v2.y - m2.y * e2.y));
        }
    }
    __syncthreads();
    if (tid < DD)
        o_rc[(size_t)b * DD + tid] = s_rc[0][tid] + s_rc[1][tid] + s_rc[2][tid] + s_rc[3][tid];
}

// ---------------------------------------------------------------------------
extern "C" void kernel_launch(void* const* d_in, const int* in_sizes, int n_in,
                              void* d_out, int out_size)
{
    const float* mem = (const float*)d_in[0];
    const float* rk  = (const float*)d_in[1];
    const float* wk  = (const float*)d_in[2];
    const float* wv  = (const float*)d_in[3];
    const float* er  = (const float*)d_in[4];

    float* out  = (float*)d_out;
    float* o_rc = out;                                   // (B, D)
    float* o_rw = o_rc + (size_t)BB * DD;                // (B, H, N)
    float* o_nm = o_rw + (size_t)BB * HH * NN;           // (B, N, D)
    float* o_ww = o_nm + (size_t)BB * NN * DD;           // (B, H, N)

    k1_stream<<<dim3(NT, BB), 256>>>(mem, rk, wk, o_nm, o_rw, o_ww);
    k2_apply<<<BB, 256>>>(mem, wv, er, o_rc, o_rw, o_nm, o_ww);
}